// round 3
// baseline (speedup 1.0000x reference)
#include <cuda_runtime.h>

#define N_VOX 1000000
#define KVOL  27
#define C_IN  3
#define C_HID 64
#define C_OUT 3
#define BN_EPS 1e-5f
#define PTS   4          // points per thread (conv1)
#define TPB   256
#define PPB   (PTS*TPB)
#define TILE_M 104       // conv2a M-tile (13 pt-groups of 8)

// Scratch (device globals: allocation-free per harness rules)
__device__ float  g_h[(size_t)N_VOX * C_HID];   // 256 MB: conv1 output (pre-BN)
__device__ float4 g_z[(size_t)KVOL * N_VOX];    // 432 MB: z[k][m] = hact[m] @ W2[26-k]
__device__ float  g_stats[4 * C_HID];           // sum, sumsq, scale, shift

typedef unsigned long long u64;

__device__ __forceinline__ u64 pack2(float lo, float hi) {
    u64 r; asm("mov.b64 %0, {%1, %2};" : "=l"(r) : "f"(lo), "f"(hi)); return r;
}
__device__ __forceinline__ void unpack2(u64 v, float& lo, float& hi) {
    asm("mov.b64 {%0, %1}, %2;" : "=f"(lo), "=f"(hi) : "l"(v));
}
#define FMA2(d, a, b, c) asm("fma.rn.f32x2 %0, %1, %2, %3;" : "=l"(d) : "l"(a), "l"(b), "l"(c))

// ---------------------------------------------------------------------------
__global__ void zero_stats_kernel() {
    int i = threadIdx.x;
    if (i < 2 * C_HID) g_stats[i] = 0.f;
}

// ---------------------------------------------------------------------------
// conv1: h[n,:] = sum_k feats[nbr[k,n]] @ W1[k]   (masked), 4 pts/thread
__global__ __launch_bounds__(TPB) void conv1_kernel(const float* __restrict__ feats,
                                                    const float* __restrict__ W1,
                                                    const int*   __restrict__ nbr) {
    __shared__ u64 w1s[KVOL * C_IN * C_HID / 2];   // [k][c][pair]
    {
        const u64* w1g = (const u64*)W1;
        for (int i = threadIdx.x; i < KVOL * C_IN * C_HID / 2; i += TPB) w1s[i] = w1g[i];
    }
    __syncthreads();
    const int base = blockIdx.x * PPB + threadIdx.x;

    #pragma unroll 1
    for (int chunk = 0; chunk < 4; chunk++) {
        u64 acc[PTS][8];
        #pragma unroll
        for (int i = 0; i < PTS; i++)
            #pragma unroll
            for (int p = 0; p < 8; p++) acc[i][p] = 0ull;

        #pragma unroll 1
        for (int k = 0; k < KVOL; k++) {
            float f[PTS][3];
            #pragma unroll
            for (int i = 0; i < PTS; i++) {
                int n = base + i * TPB;
                int idx = (n < N_VOX) ? __ldg(&nbr[(size_t)k * N_VOX + n]) : -1;
                if (idx >= 0) {
                    f[i][0] = __ldg(&feats[3 * idx + 0]);
                    f[i][1] = __ldg(&feats[3 * idx + 1]);
                    f[i][2] = __ldg(&feats[3 * idx + 2]);
                } else {
                    f[i][0] = 0.f; f[i][1] = 0.f; f[i][2] = 0.f;
                }
            }
            const u64* w = w1s + k * 96 + chunk * 8;
            #pragma unroll
            for (int i = 0; i < PTS; i++) {
                u64 a0 = pack2(f[i][0], f[i][0]);
                u64 a1 = pack2(f[i][1], f[i][1]);
                u64 a2 = pack2(f[i][2], f[i][2]);
                #pragma unroll
                for (int p = 0; p < 8; p++) {
                    FMA2(acc[i][p], a0, w[p],      acc[i][p]);
                    FMA2(acc[i][p], a1, w[32 + p], acc[i][p]);
                    FMA2(acc[i][p], a2, w[64 + p], acc[i][p]);
                }
            }
        }
        #pragma unroll
        for (int i = 0; i < PTS; i++) {
            int n = base + i * TPB;
            if (n < N_VOX) {
                ulonglong2* ho = (ulonglong2*)(g_h + (size_t)n * C_HID + chunk * 16);
                #pragma unroll
                for (int j = 0; j < 4; j++)
                    ho[j] = make_ulonglong2(acc[i][2 * j], acc[i][2 * j + 1]);
            }
        }
    }
}

// ---------------------------------------------------------------------------
// BN stats: per-channel sum / sumsq over all N rows of g_h
__global__ __launch_bounds__(256) void stats_kernel() {
    int d = threadIdx.x & 63;
    int r = threadIdx.x >> 6;
    float s = 0.f, s2 = 0.f;
    for (size_t n = (size_t)blockIdx.x * 4 + r; n < N_VOX; n += (size_t)gridDim.x * 4) {
        float v = g_h[n * C_HID + d];
        s += v; s2 += v * v;
    }
    __shared__ float sm[8][C_HID];
    sm[r][d] = s; sm[4 + r][d] = s2;
    __syncthreads();
    if (r == 0) {
        s  = sm[0][d] + sm[1][d] + sm[2][d] + sm[3][d];
        s2 = sm[4][d] + sm[5][d] + sm[6][d] + sm[7][d];
        atomicAdd(&g_stats[d], s);
        atomicAdd(&g_stats[C_HID + d], s2);
    }
}

__global__ void finalize_kernel(const float* __restrict__ gamma,
                                const float* __restrict__ beta) {
    int d = threadIdx.x;
    if (d < C_HID) {
        float mu  = g_stats[d] * (1.f / N_VOX);
        float var = g_stats[C_HID + d] * (1.f / N_VOX) - mu * mu;
        float sc  = gamma[d] * rsqrtf(var + BN_EPS);
        g_stats[2 * C_HID + d] = sc;
        g_stats[3 * C_HID + d] = beta[d] - mu * sc;
    }
}

// ---------------------------------------------------------------------------
// conv2a as GEMM: Z[m, 81] = relu(bn(H[m, 64])) x Wt[64, 81],
// Wt[:, k*3+c] = W2[26-k][:, c]. Block: 128 thr, M-tile 104.
// Thread tile: 8 pts x 9 outs (3 k x 3 c), d-pair packed accumulators.
// Smem transposed to [d-pair][...] for conflict-free broadcast LDS.
__global__ __launch_bounds__(128) void conv2a_kernel(const float* __restrict__ W2) {
    __shared__ u64 Hs[32][TILE_M + 1];   // +1 pad: STS 2-way instead of 16-way
    __shared__ u64 Ws[32][81];
    __shared__ float scs[C_HID], shs[C_HID];
    const int tid = threadIdx.x;

    if (tid < C_HID) {
        scs[tid] = g_stats[2 * C_HID + tid];
        shs[tid] = g_stats[3 * C_HID + tid];
    }
    for (int i = tid; i < 32 * 81; i += 128) {
        int p = i / 81, o = i % 81;
        int k = o / 3, c = o % 3;
        const float* wsrc = W2 + (size_t)(KVOL - 1 - k) * (C_HID * C_OUT);
        Ws[p][o] = pack2(wsrc[(2 * p) * 3 + c], wsrc[(2 * p + 1) * 3 + c]);
    }
    __syncthreads();

    const size_t mbase = (size_t)blockIdx.x * TILE_M;

    // Stage H tile with fused BN+ReLU (coalesced LDG.64 per thread)
    for (int i = tid; i < TILE_M * 32; i += 128) {
        int row = i >> 5, p = i & 31;
        size_t m = mbase + row;
        u64 v = 0ull;
        if (m < N_VOX) {
            const float2 hv = *(const float2*)(g_h + m * C_HID + 2 * p);
            float a = fmaxf(fmaf(hv.x, scs[2 * p],     shs[2 * p]),     0.f);
            float b = fmaxf(fmaf(hv.y, scs[2 * p + 1], shs[2 * p + 1]), 0.f);
            v = pack2(a, b);
        }
        Hs[p][row] = v;
    }
    __syncthreads();

    if (tid >= 117) return;             // 13 pt-groups x 9 out-groups
    const int og = tid % 9;
    const int pg = tid / 9;

    u64 acc[8][9];
    #pragma unroll
    for (int j = 0; j < 8; j++)
        #pragma unroll
        for (int o = 0; o < 9; o++) acc[j][o] = 0ull;

    #pragma unroll 4
    for (int p = 0; p < 32; p++) {
        u64 h[8];
        #pragma unroll
        for (int j = 0; j < 8; j++) h[j] = Hs[p][pg * 8 + j];
        #pragma unroll
        for (int o = 0; o < 9; o++) {
            u64 w = Ws[p][og * 9 + o];
            #pragma unroll
            for (int j = 0; j < 8; j++) FMA2(acc[j][o], h[j], w, acc[j][o]);
        }
    }

    #pragma unroll
    for (int j = 0; j < 8; j++) {
        size_t m = mbase + pg * 8 + j;
        if (m < N_VOX) {
            #pragma unroll
            for (int kk = 0; kk < 3; kk++) {
                float x0, x1, y0, y1, z0, z1;
                unpack2(acc[j][kk * 3 + 0], x0, x1);
                unpack2(acc[j][kk * 3 + 1], y0, y1);
                unpack2(acc[j][kk * 3 + 2], z0, z1);
                int k = og * 3 + kk;
                g_z[(size_t)k * N_VOX + m] = make_float4(x0 + x1, y0 + y1, z0 + z1, 0.f);
            }
        }
    }
}

// ---------------------------------------------------------------------------
// conv2b: out[n] = sum_k valid(k,n) * z[k, nbr[k,n]]   (16B gathers)
__global__ __launch_bounds__(256) void conv2b_kernel(const int* __restrict__ nbr,
                                                     float* __restrict__ out) {
    int n = blockIdx.x * 256 + threadIdx.x;
    if (n >= N_VOX) return;
    float a0 = 0.f, a1 = 0.f, a2 = 0.f;
    #pragma unroll
    for (int k = 0; k < KVOL; k++) {
        int idx = __ldg(&nbr[(size_t)k * N_VOX + n]);
        if (idx >= 0) {
            float4 v = __ldg(&g_z[(size_t)k * N_VOX + idx]);
            a0 += v.x; a1 += v.y; a2 += v.z;
        }
    }
    out[3 * n + 0] = a0;
    out[3 * n + 1] = a1;
    out[3 * n + 2] = a2;
}

// ---------------------------------------------------------------------------
extern "C" void kernel_launch(void* const* d_in, const int* in_sizes, int n_in,
                              void* d_out, int out_size) {
    const float* feats = (const float*)d_in[0];
    const float* W1    = (const float*)d_in[1];
    const float* gamma = (const float*)d_in[2];
    const float* beta  = (const float*)d_in[3];
    const float* W2    = (const float*)d_in[4];
    const int*   nbr   = (const int*)  d_in[5];
    float*       out   = (float*)d_out;

    zero_stats_kernel<<<1, 128>>>();
    conv1_kernel<<<(N_VOX + PPB - 1) / PPB, TPB>>>(feats, W1, nbr);
    stats_kernel<<<2048, 256>>>();
    finalize_kernel<<<1, 64>>>(gamma, beta);
    conv2a_kernel<<<(N_VOX + TILE_M - 1) / TILE_M, 128>>>(W2);
    conv2b_kernel<<<(N_VOX + 255) / 256, 256>>>(nbr, out);
}

// round 4
// speedup vs baseline: 1.2668x; 1.2668x over previous
#include <cuda_runtime.h>

#define N_VOX 1000000
#define KVOL  27
#define C_IN  3
#define C_HID 64
#define C_OUT 3
#define BN_EPS 1e-5f

// Scratch (device globals: allocation-free per harness rules)
__device__ float g_h[(size_t)N_VOX * C_HID];   // 256 MB: conv1 out, then BN+ReLU in-place
__device__ float g_stats[4 * C_HID];           // sum, sumsq, scale, shift

typedef unsigned long long u64;

__device__ __forceinline__ u64 pack2(float lo, float hi) {
    u64 r; asm("mov.b64 %0, {%1, %2};" : "=l"(r) : "f"(lo), "f"(hi)); return r;
}
__device__ __forceinline__ void unpack2(u64 v, float& lo, float& hi) {
    asm("mov.b64 {%0, %1}, %2;" : "=f"(lo), "=f"(hi) : "l"(v));
}
#define FMA2(d, a, b, c) asm("fma.rn.f32x2 %0, %1, %2, %3;" : "=l"(d) : "l"(a), "l"(b), "l"(c))

// ---------------------------------------------------------------------------
__global__ void zero_stats_kernel() {
    int i = threadIdx.x;
    if (i < 2 * C_HID) g_stats[i] = 0.f;
}
__global__ void dummy_kernel() {}   // shifts ncu's skip-count onto conv1

// ---------------------------------------------------------------------------
// conv1: h[n,:] = sum_k feats[nbr[k,n]] @ W1[k]  — single pass, 64-ch acc
__global__ __launch_bounds__(256) void conv1_kernel(const float* __restrict__ feats,
                                                    const float* __restrict__ W1,
                                                    const int*   __restrict__ nbr) {
    __shared__ u64 w1s[KVOL * C_IN * C_HID / 2];   // [k][c][pair]
    {
        const u64* w1g = (const u64*)W1;
        for (int i = threadIdx.x; i < KVOL * C_IN * C_HID / 2; i += 256) w1s[i] = w1g[i];
    }
    __syncthreads();
    int n = blockIdx.x * 256 + threadIdx.x;
    if (n >= N_VOX) return;

    u64 acc[32];
    #pragma unroll
    for (int p = 0; p < 32; p++) acc[p] = 0ull;

    #pragma unroll 1
    for (int k = 0; k < KVOL; k++) {
        int id = __ldg(&nbr[(size_t)k * N_VOX + n]);
        if (id >= 0) {
            float f0 = __ldg(&feats[3 * id + 0]);
            float f1 = __ldg(&feats[3 * id + 1]);
            float f2 = __ldg(&feats[3 * id + 2]);
            u64 a0 = pack2(f0, f0);
            u64 a1 = pack2(f1, f1);
            u64 a2 = pack2(f2, f2);
            const u64* w = w1s + k * 96;
            #pragma unroll
            for (int p = 0; p < 32; p++) {
                FMA2(acc[p], a0, w[p],      acc[p]);
                FMA2(acc[p], a1, w[32 + p], acc[p]);
                FMA2(acc[p], a2, w[64 + p], acc[p]);
            }
        }
    }
    ulonglong2* ho = (ulonglong2*)(g_h + (size_t)n * C_HID);
    #pragma unroll
    for (int j = 0; j < 16; j++)
        ho[j] = make_ulonglong2(acc[2 * j], acc[2 * j + 1]);
}

// ---------------------------------------------------------------------------
// BN stats: per-channel sum / sumsq over all N rows of g_h
__global__ __launch_bounds__(256) void stats_kernel() {
    int d = threadIdx.x & 63;
    int r = threadIdx.x >> 6;
    float s = 0.f, s2 = 0.f;
    for (size_t n = (size_t)blockIdx.x * 4 + r; n < N_VOX; n += (size_t)gridDim.x * 4) {
        float v = g_h[n * C_HID + d];
        s += v; s2 += v * v;
    }
    __shared__ float sm[8][C_HID];
    sm[r][d] = s; sm[4 + r][d] = s2;
    __syncthreads();
    if (r == 0) {
        s  = sm[0][d] + sm[1][d] + sm[2][d] + sm[3][d];
        s2 = sm[4][d] + sm[5][d] + sm[6][d] + sm[7][d];
        atomicAdd(&g_stats[d], s);
        atomicAdd(&g_stats[C_HID + d], s2);
    }
}

__global__ void finalize_kernel(const float* __restrict__ gamma,
                                const float* __restrict__ beta) {
    int d = threadIdx.x;
    if (d < C_HID) {
        float mu  = g_stats[d] * (1.f / N_VOX);
        float var = g_stats[C_HID + d] * (1.f / N_VOX) - mu * mu;
        float sc  = gamma[d] * rsqrtf(var + BN_EPS);
        g_stats[2 * C_HID + d] = sc;
        g_stats[3 * C_HID + d] = beta[d] - mu * sc;
    }
}

// ---------------------------------------------------------------------------
// BN + ReLU applied in-place to g_h (safe: conv1 rewrites g_h every replay)
__global__ __launch_bounds__(256) void bnrelu_kernel() {
    __shared__ float scs[C_HID], shs[C_HID];
    if (threadIdx.x < C_HID) {
        scs[threadIdx.x] = g_stats[2 * C_HID + threadIdx.x];
        shs[threadIdx.x] = g_stats[3 * C_HID + threadIdx.x];
    }
    __syncthreads();
    const size_t total = (size_t)N_VOX * (C_HID / 4);
    float4* h4 = (float4*)g_h;
    for (size_t e = (size_t)blockIdx.x * 256 + threadIdx.x; e < total;
         e += (size_t)gridDim.x * 256) {
        int j = (int)(e & 15);
        float4 v = h4[e];
        v.x = fmaxf(fmaf(v.x, scs[4 * j + 0], shs[4 * j + 0]), 0.f);
        v.y = fmaxf(fmaf(v.y, scs[4 * j + 1], shs[4 * j + 1]), 0.f);
        v.z = fmaxf(fmaf(v.z, scs[4 * j + 2], shs[4 * j + 2]), 0.f);
        v.w = fmaxf(fmaf(v.w, scs[4 * j + 3], shs[4 * j + 3]), 0.f);
        h4[e] = v;
    }
}

// ---------------------------------------------------------------------------
// conv2 (fused): out[n] = sum_k valid * ( hact[nbr[k,n]] @ W2[26-k] )
// 16-lane teams: team owns point n; each lane loads a coalesced 16B chunk of
// the neighbor row (LDG.128), does 6 packed FMAs against smem weights, and a
// 16-lane shuffle reduction produces the 3 outputs. Validity is team-uniform,
// so the heavy block executes with P(any of 2 teams) ~= 0.25 per k.
#define PBLK 128   // points per block (256 thr, 8 warps * 8 pairs * 2 pts)
__global__ __launch_bounds__(256) void conv2_kernel(const float* __restrict__ W2,
                                                    const int*   __restrict__ nbr,
                                                    float* __restrict__ out) {
    __shared__ u64 w2t[KVOL * C_OUT * C_HID / 2];   // [k][c][pair], k -> W2[26-k]
    __shared__ int idxs[KVOL * PBLK];
    const int tid = threadIdx.x;
    {
        float* w2tf = (float*)w2t;
        for (int i = tid; i < KVOL * C_OUT * C_HID; i += 256) {
            int kk  = i / (C_OUT * C_HID);
            int rem = i % (C_OUT * C_HID);
            int c   = rem / C_HID;
            int d   = rem % C_HID;
            w2tf[(kk * C_OUT + c) * C_HID + d] =
                W2[(size_t)(KVOL - 1 - kk) * (C_HID * C_OUT) + d * C_OUT + c];
        }
    }
    const int base = blockIdx.x * PBLK;
    for (int i = tid; i < KVOL * PBLK; i += 256) {
        int k = i / PBLK, pl = i % PBLK;
        int n = base + pl;
        idxs[i] = (n < N_VOX) ? __ldg(&nbr[(size_t)k * N_VOX + n]) : -1;
    }
    __syncthreads();

    const int lane  = tid & 31;
    const int wrp   = tid >> 5;
    const int tlane = lane & 15;
    const int half  = lane >> 4;

    #pragma unroll 1
    for (int pp = 0; pp < PBLK / 16; pp++) {       // 8 pairs per warp
        const int pl = (wrp * (PBLK / 16) + pp) * 2 + half;
        const int n  = base + pl;

        u64 acc0 = 0ull, acc1 = 0ull, acc2 = 0ull;
        #pragma unroll 1
        for (int k = 0; k < KVOL; k++) {
            int id = idxs[k * PBLK + pl];
            if (id >= 0) {
                ulonglong2 hv = __ldg((const ulonglong2*)(g_h + (size_t)id * C_HID) + tlane);
                const ulonglong2* wb = (const ulonglong2*)(w2t + k * 96 + 2 * tlane);
                ulonglong2 w0 = wb[0], w1 = wb[16], w2v = wb[32];
                FMA2(acc0, hv.x, w0.x,  acc0); FMA2(acc0, hv.y, w0.y,  acc0);
                FMA2(acc1, hv.x, w1.x,  acc1); FMA2(acc1, hv.y, w1.y,  acc1);
                FMA2(acc2, hv.x, w2v.x, acc2); FMA2(acc2, hv.y, w2v.y, acc2);
            }
        }
        float r0, r1, r2;
        { float lo, hi; unpack2(acc0, lo, hi); r0 = lo + hi; }
        { float lo, hi; unpack2(acc1, lo, hi); r1 = lo + hi; }
        { float lo, hi; unpack2(acc2, lo, hi); r2 = lo + hi; }
        #pragma unroll
        for (int o = 8; o >= 1; o >>= 1) {
            r0 += __shfl_xor_sync(0xffffffffu, r0, o);
            r1 += __shfl_xor_sync(0xffffffffu, r1, o);
            r2 += __shfl_xor_sync(0xffffffffu, r2, o);
        }
        if (tlane == 0 && n < N_VOX) {
            out[3 * n + 0] = r0;
            out[3 * n + 1] = r1;
            out[3 * n + 2] = r2;
        }
    }
}

// ---------------------------------------------------------------------------
extern "C" void kernel_launch(void* const* d_in, const int* in_sizes, int n_in,
                              void* d_out, int out_size) {
    const float* feats = (const float*)d_in[0];
    const float* W1    = (const float*)d_in[1];
    const float* gamma = (const float*)d_in[2];
    const float* beta  = (const float*)d_in[3];
    const float* W2    = (const float*)d_in[4];
    const int*   nbr   = (const int*)  d_in[5];
    float*       out   = (float*)d_out;

    zero_stats_kernel<<<1, 128>>>();                       // 0
    dummy_kernel<<<1, 32>>>();                             // 1
    dummy_kernel<<<1, 32>>>();                             // 2
    conv1_kernel<<<(N_VOX + 255) / 256, 256>>>(feats, W1, nbr);   // 3 <- ncu lands here
    stats_kernel<<<2048, 256>>>();                         // 4
    finalize_kernel<<<1, 64>>>(gamma, beta);               // 5
    bnrelu_kernel<<<4096, 256>>>();                        // 6
    conv2_kernel<<<(N_VOX + PBLK - 1) / PBLK, 256>>>(W2, nbr, out); // 7
}